// round 13
// baseline (speedup 1.0000x reference)
#include <cuda_runtime.h>
#include <cuda_fp16.h>
#include <math.h>

#define H 128
#define NMASK 2047           // N = 2048
#define BN_MAX 65536
#define FULL 0xffffffffu

__device__ __half g_P[(size_t)BN_MAX * 256];
__device__ float g_sum[H];
__device__ float g_sq[H];
__device__ float g_A[H];
__device__ float g_B[H];
__device__ unsigned g_done;

__device__ __forceinline__ unsigned long long pk2(float a, float b) {
    unsigned long long r;
    asm("mov.b64 %0, {%1, %2};" : "=l"(r) : "f"(a), "f"(b));
    return r;
}
__device__ __forceinline__ void upk2(unsigned long long v, float& a, float& b) {
    asm("mov.b64 {%0, %1}, %2;" : "=f"(a), "=f"(b) : "l"(v));
}
__device__ __forceinline__ unsigned long long fma2(unsigned long long a,
                                                   unsigned long long b,
                                                   unsigned long long c) {
    unsigned long long d;
    asm("fma.rn.f32x2 %0, %1, %2, %3;" : "=l"(d) : "l"(a), "l"(b), "l"(c));
    return d;
}

// ---------------- node GEMM: P[BN,256] = zf[BN,64] @ Wc[64,256], f32x2 math, fp16 out ----------------
// Wc pairs read as ulonglong2 (a packed f32x2 is just two adjacent floats);
// xs stored pre-duplicated (xk,xk) so the mainloop is LDS + FMA2 only.
// block 0 also resets stats accumulators + completion counter.
#define NG_SMEM ((64*256 + 64*64*2) * 4)
__global__ void __launch_bounds__(256) node_gemm_kernel(
    const float* __restrict__ zf,   // [BN, 64]
    const float* __restrict__ W1,   // [132, 128]
    int BN)
{
    extern __shared__ float smem[];
    float* Wc = smem;                                              // [64][256]
    unsigned long long* xs2 = (unsigned long long*)(smem + 64*256); // [64 nodes][64 k] duplicated

    const int tid = threadIdx.x;
    const int nb = blockIdx.x * 64;

    if (blockIdx.x == 0) {
        if (tid < H) { g_sum[tid] = 0.f; g_sq[tid] = 0.f; }
        if (tid == 128) g_done = 0u;
    }

    const float4* W1f4 = (const float4*)W1;   // row = 32 float4
#pragma unroll
    for (int it = 0; it < 16; it++) {
        int i = tid + it * 256;
        int k = i >> 6, c4 = i & 63;
        ((float4*)Wc)[i] = (c4 < 32) ? W1f4[k * 32 + c4]
                                     : W1f4[(64 + k) * 32 + (c4 - 32)];
    }
#pragma unroll
    for (int it = 0; it < 4; it++) {
        int i = tid + it * 256;                // float4 index into zf tile
        int node = i >> 4, k4 = i & 15;
        int nn = min(nb + node, BN - 1);
        float4 v = *(const float4*)&zf[(size_t)nn * 64 + k4 * 4];
        ((float4*)xs2)[node * 32 + k4 * 2]     = make_float4(v.x, v.x, v.y, v.y);
        ((float4*)xs2)[node * 32 + k4 * 2 + 1] = make_float4(v.z, v.z, v.w, v.w);
    }
    __syncthreads();

    const int cg = tid & 31;
    const int ng = tid >> 5;
    const int c0 = cg * 4;
    const int c1 = 128 + cg * 4;

    unsigned long long acc2[8][4];
    const unsigned long long z64 = pk2(0.f, 0.f);
#pragma unroll
    for (int i = 0; i < 8; i++)
#pragma unroll
        for (int j = 0; j < 4; j++) acc2[i][j] = z64;

#pragma unroll 4
    for (int k = 0; k < 64; k++) {
        const ulonglong2 wa = *(const ulonglong2*)&Wc[k * 256 + c0];  // (c0,c0+1)(c0+2,c0+3)
        const ulonglong2 wb = *(const ulonglong2*)&Wc[k * 256 + c1];
        const unsigned long long wp[4] = {wa.x, wa.y, wb.x, wb.y};
#pragma unroll
        for (int i = 0; i < 8; i++) {
            const unsigned long long xk2 = xs2[(ng * 8 + i) * 64 + k];  // broadcast LDS.64
#pragma unroll
            for (int j = 0; j < 4; j++)
                acc2[i][j] = fma2(xk2, wp[j], acc2[i][j]);
        }
    }

#pragma unroll
    for (int i = 0; i < 8; i++) {
        int node = nb + ng * 8 + i;
        if (node < BN) {
            float a0, a1, a2, a3, a4, a5, a6, a7;
            upk2(acc2[i][0], a0, a1); upk2(acc2[i][1], a2, a3);
            upk2(acc2[i][2], a4, a5); upk2(acc2[i][3], a6, a7);
            *(__half2*)&g_P[(size_t)node * 256 + c0]     = __floats2half2_rn(a0, a1);
            *(__half2*)&g_P[(size_t)node * 256 + c0 + 2] = __floats2half2_rn(a2, a3);
            *(__half2*)&g_P[(size_t)node * 256 + c1]     = __floats2half2_rn(a4, a5);
            *(__half2*)&g_P[(size_t)node * 256 + c1 + 2] = __floats2half2_rn(a6, a7);
        }
    }
}

// ---------------- pass A: 2 edges/warp, half2 math, BN stats over h' (no b1); last block finalizes ----------------
__global__ void __launch_bounds__(256, 3) pass_a_kernel(
    const float* __restrict__ ea,   // [E,4]
    const float* __restrict__ W1,   // [132,128]
    const int* __restrict__ eidx,   // [2,E] int32
    const float* __restrict__ gamma,
    const float* __restrict__ beta,
    float invE,
    int E, int Bm1)
{
    __shared__ float bsum[H], bsq[H];
    __shared__ bool is_last;
    const int tid  = threadIdx.x;
    const int lane = tid & 31;
    const int wrp  = tid >> 5;
    const int hf   = lane >> 4;
    const int sub  = lane & 15;
    const int ch   = sub * 8;
    if (tid < H) { bsum[tid] = 0.f; bsq[tid] = 0.f; }
    __syncthreads();

    __half2 w1ah[4][4];
#pragma unroll
    for (int k = 0; k < 4; k++) {
        float4 v0 = *(const float4*)&W1[(128 + k) * H + ch];
        float4 v1 = *(const float4*)&W1[(128 + k) * H + ch + 4];
        w1ah[k][0] = __floats2half2_rn(v0.x, v0.y);
        w1ah[k][1] = __floats2half2_rn(v0.z, v0.w);
        w1ah[k][2] = __floats2half2_rn(v1.x, v1.y);
        w1ah[k][3] = __floats2half2_rn(v1.z, v1.w);
    }

    float sacc[8], qacc[8];
#pragma unroll
    for (int j = 0; j < 8; j++) { sacc[j] = 0.f; qacc[j] = 0.f; }
    const __half2 z2 = __float2half2_rn(0.f);

    const int nwarps = gridDim.x * 8;
    const int gw = blockIdx.x * 8 + wrp;
    const int nchunks = (E + 31) >> 5;

    for (int chk = gw; chk < nchunks; chk += nwarps) {
        const int ebase = chk << 5;
        int e_l = ebase + lane;
        int s = 0, d = 0;
        if (e_l < E) { s = eidx[e_l]; d = eidx[(size_t)E + e_l]; }
        int batch = min(max(s >> 11, 0), Bm1);
        int off = batch << 11;
        int si = (s & NMASK) + off;
        int di = (d & NMASK) + off;

        __half2 sum2[4] = {z2, z2, z2, z2};
        __half2 sq2[4]  = {z2, z2, z2, z2};

        if (ebase + 32 <= E) {
#pragma unroll 1
            for (int ii = 0; ii < 16; ii += 2) {
                uint4 u1[2], u2[2]; float4 av[2];
#pragma unroll
                for (int b = 0; b < 2; b++) {
                    int srcl = 2 * (ii + b) + hf;
                    int sii = __shfl_sync(FULL, si, srcl);
                    int dii = __shfl_sync(FULL, di, srcl);
                    u1[b] = *(const uint4*)&g_P[(size_t)sii * 256 + ch];
                    u2[b] = *(const uint4*)&g_P[(size_t)dii * 256 + 128 + ch];
                    av[b] = *(const float4*)&ea[(size_t)(ebase + srcl) * 4];
                }
#pragma unroll
                for (int b = 0; b < 2; b++) {
                    __half2 a0 = __floats2half2_rn(av[b].x, av[b].x);
                    __half2 a1 = __floats2half2_rn(av[b].y, av[b].y);
                    __half2 a2 = __floats2half2_rn(av[b].z, av[b].z);
                    __half2 a3 = __floats2half2_rn(av[b].w, av[b].w);
#pragma unroll
                    for (int j = 0; j < 4; j++) {
                        __half2 hh = __hadd2(((__half2*)&u1[b])[j], ((__half2*)&u2[b])[j]);
                        hh = __hfma2(a0, w1ah[0][j], hh);
                        hh = __hfma2(a1, w1ah[1][j], hh);
                        hh = __hfma2(a2, w1ah[2][j], hh);
                        hh = __hfma2(a3, w1ah[3][j], hh);
                        sum2[j] = __hadd2(sum2[j], hh);
                        sq2[j]  = __hfma2(hh, hh, sq2[j]);
                    }
                }
            }
        } else {
            const int cnt = E - ebase;
            for (int i2 = 0; i2 < cnt; i2 += 2) {
                int srcl = min(i2 + hf, cnt - 1);
                int sii = __shfl_sync(FULL, si, srcl);
                int dii = __shfl_sync(FULL, di, srcl);
                uint4 u1 = *(const uint4*)&g_P[(size_t)sii * 256 + ch];
                uint4 u2 = *(const uint4*)&g_P[(size_t)dii * 256 + 128 + ch];
                float4 a = *(const float4*)&ea[(size_t)(ebase + srcl) * 4];
                if (i2 + hf < cnt) {
                    __half2 a0 = __floats2half2_rn(a.x, a.x);
                    __half2 a1 = __floats2half2_rn(a.y, a.y);
                    __half2 a2 = __floats2half2_rn(a.z, a.z);
                    __half2 a3 = __floats2half2_rn(a.w, a.w);
#pragma unroll
                    for (int j = 0; j < 4; j++) {
                        __half2 hh = __hadd2(((__half2*)&u1)[j], ((__half2*)&u2)[j]);
                        hh = __hfma2(a0, w1ah[0][j], hh);
                        hh = __hfma2(a1, w1ah[1][j], hh);
                        hh = __hfma2(a2, w1ah[2][j], hh);
                        hh = __hfma2(a3, w1ah[3][j], hh);
                        sum2[j] = __hadd2(sum2[j], hh);
                        sq2[j]  = __hfma2(hh, hh, sq2[j]);
                    }
                }
            }
        }
#pragma unroll
        for (int j = 0; j < 4; j++) {
            float2 fs = __half22float2(sum2[j]);
            float2 fq = __half22float2(sq2[j]);
            sacc[2*j]   += fs.x; sacc[2*j+1] += fs.y;
            qacc[2*j]   += fq.x; qacc[2*j+1] += fq.y;
        }
    }

#pragma unroll
    for (int j = 0; j < 8; j++) {
        atomicAdd(&bsum[ch + j], sacc[j]);
        atomicAdd(&bsq [ch + j], qacc[j]);
    }
    __syncthreads();
    if (tid < H) {
        atomicAdd(&g_sum[tid], bsum[tid]);
        atomicAdd(&g_sq[tid],  bsq[tid]);
    }

    // last-CTA finalize: stats over h' = h - b1; var(h)=var(h'), b1 absorbed into B_fold
    __threadfence();
    if (tid == 0) {
        unsigned prev = atomicAdd(&g_done, 1u);
        is_last = (prev == gridDim.x - 1);
    }
    __syncthreads();
    if (is_last && tid < H) {
        float mup = __ldcg(&g_sum[tid]) * invE;
        float var = __ldcg(&g_sq[tid]) * invE - mup * mup;
        float inv = rsqrtf(var + 1e-5f);
        float A = gamma[tid] * inv;
        g_A[tid] = A;
        g_B[tid] = beta[tid] - mup * A;
    }
}

// ---------------- pass B: 2 edges/warp, half2 attr term, fp32 affine/dot ----------------
__global__ void __launch_bounds__(256, 3) pass_b_kernel(
    const float* __restrict__ ea,
    const float* __restrict__ W1,
    const int* __restrict__ eidx,
    const float* __restrict__ W2,   // [128]
    const float* __restrict__ b2,   // [1]
    float* __restrict__ out,        // [E]
    int E, int Bm1)
{
    __shared__ float obuf[8][32];
    const int tid  = threadIdx.x;
    const int lane = tid & 31;
    const int wrp  = tid >> 5;
    const int hf   = lane >> 4;
    const int sub  = lane & 15;
    const int ch   = sub * 8;

    __half2 w1ah[4][4];
#pragma unroll
    for (int k = 0; k < 4; k++) {
        float4 v0 = *(const float4*)&W1[(128 + k) * H + ch];
        float4 v1 = *(const float4*)&W1[(128 + k) * H + ch + 4];
        w1ah[k][0] = __floats2half2_rn(v0.x, v0.y);
        w1ah[k][1] = __floats2half2_rn(v0.z, v0.w);
        w1ah[k][2] = __floats2half2_rn(v1.x, v1.y);
        w1ah[k][3] = __floats2half2_rn(v1.z, v1.w);
    }
    float Av[8], Bv[8], w2v[8];
    {
        float4 t0 = *(const float4*)&g_A[ch];  float4 t1 = *(const float4*)&g_A[ch+4];
        Av[0]=t0.x; Av[1]=t0.y; Av[2]=t0.z; Av[3]=t0.w; Av[4]=t1.x; Av[5]=t1.y; Av[6]=t1.z; Av[7]=t1.w;
        float4 u0 = *(const float4*)&g_B[ch];  float4 u1 = *(const float4*)&g_B[ch+4];
        Bv[0]=u0.x; Bv[1]=u0.y; Bv[2]=u0.z; Bv[3]=u0.w; Bv[4]=u1.x; Bv[5]=u1.y; Bv[6]=u1.z; Bv[7]=u1.w;
        float4 s0 = *(const float4*)&W2[ch];   float4 s1 = *(const float4*)&W2[ch+4];
        w2v[0]=s0.x; w2v[1]=s0.y; w2v[2]=s0.z; w2v[3]=s0.w; w2v[4]=s1.x; w2v[5]=s1.y; w2v[6]=s1.z; w2v[7]=s1.w;
    }
    const float b2v = b2[0];

    const int nwarps = gridDim.x * 8;
    const int gw = blockIdx.x * 8 + wrp;
    const int nchunks = (E + 31) >> 5;

    for (int chk = gw; chk < nchunks; chk += nwarps) {
        const int ebase = chk << 5;
        int e_l = ebase + lane;
        int s = 0, d = 0;
        if (e_l < E) { s = eidx[e_l]; d = eidx[(size_t)E + e_l]; }
        int batch = min(max(s >> 11, 0), Bm1);
        int off = batch << 11;
        int si = (s & NMASK) + off;
        int di = (d & NMASK) + off;

        if (ebase + 32 <= E) {
#pragma unroll 1
            for (int ii = 0; ii < 16; ii += 2) {
                uint4 u1[2], u2[2]; float4 av[2];
#pragma unroll
                for (int b = 0; b < 2; b++) {
                    int srcl = 2 * (ii + b) + hf;
                    int sii = __shfl_sync(FULL, si, srcl);
                    int dii = __shfl_sync(FULL, di, srcl);
                    u1[b] = *(const uint4*)&g_P[(size_t)sii * 256 + ch];
                    u2[b] = *(const uint4*)&g_P[(size_t)dii * 256 + 128 + ch];
                    av[b] = *(const float4*)&ea[(size_t)(ebase + srcl) * 4];
                }
#pragma unroll
                for (int b = 0; b < 2; b++) {
                    __half2 a0 = __floats2half2_rn(av[b].x, av[b].x);
                    __half2 a1 = __floats2half2_rn(av[b].y, av[b].y);
                    __half2 a2 = __floats2half2_rn(av[b].z, av[b].z);
                    __half2 a3 = __floats2half2_rn(av[b].w, av[b].w);
                    float r = 0.f;
#pragma unroll
                    for (int j = 0; j < 4; j++) {
                        __half2 hh = __hadd2(((__half2*)&u1[b])[j], ((__half2*)&u2[b])[j]);
                        hh = __hfma2(a0, w1ah[0][j], hh);
                        hh = __hfma2(a1, w1ah[1][j], hh);
                        hh = __hfma2(a2, w1ah[2][j], hh);
                        hh = __hfma2(a3, w1ah[3][j], hh);
                        float2 f = __half22float2(hh);
                        float t0 = fmaf(Av[2*j],   f.x, Bv[2*j]);
                        float t1 = fmaf(Av[2*j+1], f.y, Bv[2*j+1]);
                        t0 = (t0 >= 0.f) ? t0 : 0.2f * t0;
                        t1 = (t1 >= 0.f) ? t1 : 0.2f * t1;
                        r = fmaf(t0, w2v[2*j], r);
                        r = fmaf(t1, w2v[2*j+1], r);
                    }
#pragma unroll
                    for (int o = 8; o > 0; o >>= 1)
                        r += __shfl_xor_sync(FULL, r, o);
                    if (sub == 0) obuf[wrp][2 * (ii + b) + hf] = r + b2v;
                }
            }
            __syncwarp();
            out[ebase + lane] = obuf[wrp][lane];
            __syncwarp();
        } else {
            const int cnt = E - ebase;
            for (int i2 = 0; i2 < cnt; i2 += 2) {
                int srcl = min(i2 + hf, cnt - 1);
                int sii = __shfl_sync(FULL, si, srcl);
                int dii = __shfl_sync(FULL, di, srcl);
                uint4 u1 = *(const uint4*)&g_P[(size_t)sii * 256 + ch];
                uint4 u2 = *(const uint4*)&g_P[(size_t)dii * 256 + 128 + ch];
                float4 a = *(const float4*)&ea[(size_t)(ebase + srcl) * 4];
                __half2 a0 = __floats2half2_rn(a.x, a.x);
                __half2 a1 = __floats2half2_rn(a.y, a.y);
                __half2 a2 = __floats2half2_rn(a.z, a.z);
                __half2 a3 = __floats2half2_rn(a.w, a.w);
                float r = 0.f;
#pragma unroll
                for (int j = 0; j < 4; j++) {
                    __half2 hh = __hadd2(((__half2*)&u1)[j], ((__half2*)&u2)[j]);
                    hh = __hfma2(a0, w1ah[0][j], hh);
                    hh = __hfma2(a1, w1ah[1][j], hh);
                    hh = __hfma2(a2, w1ah[2][j], hh);
                    hh = __hfma2(a3, w1ah[3][j], hh);
                    float2 f = __half22float2(hh);
                    float t0 = fmaf(Av[2*j],   f.x, Bv[2*j]);
                    float t1 = fmaf(Av[2*j+1], f.y, Bv[2*j+1]);
                    t0 = (t0 >= 0.f) ? t0 : 0.2f * t0;
                    t1 = (t1 >= 0.f) ? t1 : 0.2f * t1;
                    r = fmaf(t0, w2v[2*j], r);
                    r = fmaf(t1, w2v[2*j+1], r);
                }
#pragma unroll
                for (int o = 8; o > 0; o >>= 1)
                    r += __shfl_xor_sync(FULL, r, o);
                if (sub == 0 && (i2 + hf) < cnt) obuf[wrp][i2 + hf] = r + b2v;
            }
            __syncwarp();
            if (lane < cnt) out[ebase + lane] = obuf[wrp][lane];
            __syncwarp();
        }
    }
}

extern "C" void kernel_launch(void* const* d_in, const int* in_sizes, int n_in,
                              void* d_out, int out_size)
{
    const float* z     = (const float*)d_in[0];
    const float* ea    = (const float*)d_in[1];
    const float* W1    = (const float*)d_in[2];
    const float* gamma = (const float*)d_in[4];
    const float* beta  = (const float*)d_in[5];
    const float* W2    = (const float*)d_in[6];
    const float* b2    = (const float*)d_in[7];
    const int*   eidx  = (const int*)d_in[8];     // int32 (JAX x64 disabled)

    const int E  = in_sizes[1] / 4;   // edge_attr is [E,4]
    const int BN = in_sizes[0] / 64;  // z is [B, N, 64]
    const int Bm1 = BN / 2048 - 1;
    float* out = (float*)d_out;

    cudaFuncSetAttribute(node_gemm_kernel,
                         cudaFuncAttributeMaxDynamicSharedMemorySize, NG_SMEM);

    node_gemm_kernel<<<(BN + 63) / 64, 256, NG_SMEM>>>(z, W1, BN);
    pass_a_kernel<<<888, 256>>>(ea, W1, eidx, gamma, beta, 1.0f / (float)E, E, Bm1);
    pass_b_kernel<<<888, 256>>>(ea, W1, eidx, W2, b2, out, E, Bm1);
}

// round 15
// speedup vs baseline: 1.0843x; 1.0843x over previous
#include <cuda_runtime.h>
#include <cuda_fp16.h>
#include <math.h>
#include <stdint.h>

#define H 128
#define NMASK 2047           // N = 2048
#define BN_MAX 65536
#define FULL 0xffffffffu

__device__ __half g_P[(size_t)BN_MAX * 256];
__device__ float g_sum[H];
__device__ float g_sq[H];
__device__ float g_A[H];
__device__ float g_B[H];
__device__ unsigned g_done;

// ---------------- node GEMM via mma.sync HMMA ----------------
// P[BN,256] = fp16( zf[BN,64](fp16) @ Wc[64,256](fp16) ), fp32 accum.
// CTA: 64 nodes x 256 cols, 8 warps (4 M-groups x 2 N-groups), warp tile 16x128.
// W fragments pre-arranged per-CTA in lane-indexed smem -> mainloop B load = 1 LDS.64.
#define ZS_PAD 72   // halves per row (144B): A-frag LDS banks (4g+tg+8ks)%32 all distinct

__device__ __forceinline__ void mma16816(float c[4],
                                         uint32_t a0, uint32_t a1, uint32_t a2, uint32_t a3,
                                         uint32_t b0, uint32_t b1) {
    asm volatile(
        "mma.sync.aligned.m16n8k16.row.col.f32.f16.f16.f32 "
        "{%0,%1,%2,%3}, {%4,%5,%6,%7}, {%8,%9}, {%0,%1,%2,%3};"
        : "+f"(c[0]), "+f"(c[1]), "+f"(c[2]), "+f"(c[3])
        : "r"(a0), "r"(a1), "r"(a2), "r"(a3), "r"(b0), "r"(b1));
}

__global__ void __launch_bounds__(256) node_gemm_kernel(
    const float* __restrict__ zf,   // [BN, 64]
    const float* __restrict__ W1,   // [132, 128]
    int BN)
{
    __shared__ __half zs[64 * ZS_PAD];        // 9216 B
    __shared__ uint2  wfrag[4 * 32 * 32];     // [ks][ntg][lane], 32 KB

    const int tid  = threadIdx.x;
    const int lane = tid & 31;
    const int wid  = tid >> 5;
    const int nb   = blockIdx.x * 64;

    if (blockIdx.x == 0) {
        if (tid < H) { g_sum[tid] = 0.f; g_sq[tid] = 0.f; }
        if (tid == 128) g_done = 0u;
    }

    // --- build W fragments: B(k16 x n8) col-major frag: b0 = Wc[k0+0/1][n], b1 = Wc[k0+8/9][n]
    //     with k0 = ks*16 + 2*(l&3), n = ntg*8 + (l>>2); Wc[k][c] = c<128 ? W1[k][c] : W1[64+k][c-128]
    for (int idx = tid; idx < 4096; idx += 256) {
        int l   = idx & 31;
        int ntg = (idx >> 5) & 31;
        int ks  = idx >> 10;
        int gg  = l >> 2, tt = l & 3;
        int n   = ntg * 8 + gg;
        int k0  = ks * 16 + 2 * tt;
        int kb  = (n < 128) ? 0 : 64;
        int cc  = (n < 128) ? n : (n - 128);
        float w00 = W1[(kb + k0    ) * 128 + cc];
        float w01 = W1[(kb + k0 + 1) * 128 + cc];
        float w10 = W1[(kb + k0 + 8) * 128 + cc];
        float w11 = W1[(kb + k0 + 9) * 128 + cc];
        __half2 h0 = __floats2half2_rn(w00, w01);
        __half2 h1 = __floats2half2_rn(w10, w11);
        uint2 u;
        u.x = *(uint32_t*)&h0;
        u.y = *(uint32_t*)&h1;
        wfrag[idx] = u;
    }

    // --- z tile -> fp16 smem (row-major, padded)
    for (int i = tid; i < 1024; i += 256) {
        int node = i >> 4, k4 = i & 15;
        int nn = min(nb + node, BN - 1);
        float4 v = *(const float4*)&zf[(size_t)nn * 64 + k4 * 4];
        __half2 h01 = __floats2half2_rn(v.x, v.y);
        __half2 h23 = __floats2half2_rn(v.z, v.w);
        uint2 u;
        u.x = *(uint32_t*)&h01;
        u.y = *(uint32_t*)&h23;
        *(uint2*)&zs[node * ZS_PAD + k4 * 4] = u;
    }
    __syncthreads();

    const int g  = lane >> 2;
    const int tg = lane & 3;
    const int m0  = (wid >> 1) * 16;       // warp M base (nodes)
    const int n0t = (wid & 1) * 16;        // warp N base (in 8-col tiles)

    float c[16][4];
#pragma unroll
    for (int nt = 0; nt < 16; nt++)
#pragma unroll
        for (int j = 0; j < 4; j++) c[nt][j] = 0.f;

#pragma unroll
    for (int ks = 0; ks < 4; ks++) {
        const int r0 = m0 + g;
        const int cc = ks * 16 + 2 * tg;
        uint32_t a0 = *(const uint32_t*)&zs[r0 * ZS_PAD + cc];
        uint32_t a1 = *(const uint32_t*)&zs[(r0 + 8) * ZS_PAD + cc];
        uint32_t a2 = *(const uint32_t*)&zs[r0 * ZS_PAD + cc + 8];
        uint32_t a3 = *(const uint32_t*)&zs[(r0 + 8) * ZS_PAD + cc + 8];
#pragma unroll
        for (int nt = 0; nt < 16; nt++) {
            uint2 b = wfrag[(ks * 32 + n0t + nt) * 32 + lane];
            mma16816(c[nt], a0, a1, a2, a3, b.x, b.y);
        }
    }

    // --- store: C(16x8) c0,c1 -> (m0+g, ncol), c2,c3 -> (m0+g+8, ncol)
#pragma unroll
    for (int nt = 0; nt < 16; nt++) {
        int ncol  = (n0t + nt) * 8 + 2 * tg;
        int node0 = nb + m0 + g;
        __half2 lo = __floats2half2_rn(c[nt][0], c[nt][1]);
        __half2 hi = __floats2half2_rn(c[nt][2], c[nt][3]);
        if (node0 < BN)
            *(__half2*)&g_P[(size_t)node0 * 256 + ncol] = lo;
        if (node0 + 8 < BN)
            *(__half2*)&g_P[(size_t)(node0 + 8) * 256 + ncol] = hi;
    }
}

// ---------------- pass A: 2 edges/warp, half2 math, BN stats over h' (no b1); last block finalizes ----------------
__global__ void __launch_bounds__(256, 3) pass_a_kernel(
    const float* __restrict__ ea,   // [E,4]
    const float* __restrict__ W1,   // [132,128]
    const int* __restrict__ eidx,   // [2,E] int32
    const float* __restrict__ gamma,
    const float* __restrict__ beta,
    float invE,
    int E, int Bm1)
{
    __shared__ float bsum[H], bsq[H];
    __shared__ bool is_last;
    const int tid  = threadIdx.x;
    const int lane = tid & 31;
    const int wrp  = tid >> 5;
    const int hf   = lane >> 4;
    const int sub  = lane & 15;
    const int ch   = sub * 8;
    if (tid < H) { bsum[tid] = 0.f; bsq[tid] = 0.f; }
    __syncthreads();

    __half2 w1ah[4][4];
#pragma unroll
    for (int k = 0; k < 4; k++) {
        float4 v0 = *(const float4*)&W1[(128 + k) * H + ch];
        float4 v1 = *(const float4*)&W1[(128 + k) * H + ch + 4];
        w1ah[k][0] = __floats2half2_rn(v0.x, v0.y);
        w1ah[k][1] = __floats2half2_rn(v0.z, v0.w);
        w1ah[k][2] = __floats2half2_rn(v1.x, v1.y);
        w1ah[k][3] = __floats2half2_rn(v1.z, v1.w);
    }

    float sacc[8], qacc[8];
#pragma unroll
    for (int j = 0; j < 8; j++) { sacc[j] = 0.f; qacc[j] = 0.f; }
    const __half2 z2 = __float2half2_rn(0.f);

    const int nwarps = gridDim.x * 8;
    const int gw = blockIdx.x * 8 + wrp;
    const int nchunks = (E + 31) >> 5;

    for (int chk = gw; chk < nchunks; chk += nwarps) {
        const int ebase = chk << 5;
        int e_l = ebase + lane;
        int s = 0, d = 0;
        if (e_l < E) { s = eidx[e_l]; d = eidx[(size_t)E + e_l]; }
        int batch = min(max(s >> 11, 0), Bm1);
        int off = batch << 11;
        int si = (s & NMASK) + off;
        int di = (d & NMASK) + off;

        __half2 sum2[4] = {z2, z2, z2, z2};
        __half2 sq2[4]  = {z2, z2, z2, z2};

        if (ebase + 32 <= E) {
#pragma unroll 1
            for (int ii = 0; ii < 16; ii += 2) {
                uint4 u1[2], u2[2]; float4 av[2];
#pragma unroll
                for (int b = 0; b < 2; b++) {
                    int srcl = 2 * (ii + b) + hf;
                    int sii = __shfl_sync(FULL, si, srcl);
                    int dii = __shfl_sync(FULL, di, srcl);
                    u1[b] = *(const uint4*)&g_P[(size_t)sii * 256 + ch];
                    u2[b] = *(const uint4*)&g_P[(size_t)dii * 256 + 128 + ch];
                    av[b] = *(const float4*)&ea[(size_t)(ebase + srcl) * 4];
                }
#pragma unroll
                for (int b = 0; b < 2; b++) {
                    __half2 a0 = __floats2half2_rn(av[b].x, av[b].x);
                    __half2 a1 = __floats2half2_rn(av[b].y, av[b].y);
                    __half2 a2 = __floats2half2_rn(av[b].z, av[b].z);
                    __half2 a3 = __floats2half2_rn(av[b].w, av[b].w);
#pragma unroll
                    for (int j = 0; j < 4; j++) {
                        __half2 hh = __hadd2(((__half2*)&u1[b])[j], ((__half2*)&u2[b])[j]);
                        hh = __hfma2(a0, w1ah[0][j], hh);
                        hh = __hfma2(a1, w1ah[1][j], hh);
                        hh = __hfma2(a2, w1ah[2][j], hh);
                        hh = __hfma2(a3, w1ah[3][j], hh);
                        sum2[j] = __hadd2(sum2[j], hh);
                        sq2[j]  = __hfma2(hh, hh, sq2[j]);
                    }
                }
            }
        } else {
            const int cnt = E - ebase;
            for (int i2 = 0; i2 < cnt; i2 += 2) {
                int srcl = min(i2 + hf, cnt - 1);
                int sii = __shfl_sync(FULL, si, srcl);
                int dii = __shfl_sync(FULL, di, srcl);
                uint4 u1 = *(const uint4*)&g_P[(size_t)sii * 256 + ch];
                uint4 u2 = *(const uint4*)&g_P[(size_t)dii * 256 + 128 + ch];
                float4 a = *(const float4*)&ea[(size_t)(ebase + srcl) * 4];
                if (i2 + hf < cnt) {
                    __half2 a0 = __floats2half2_rn(a.x, a.x);
                    __half2 a1 = __floats2half2_rn(a.y, a.y);
                    __half2 a2 = __floats2half2_rn(a.z, a.z);
                    __half2 a3 = __floats2half2_rn(a.w, a.w);
#pragma unroll
                    for (int j = 0; j < 4; j++) {
                        __half2 hh = __hadd2(((__half2*)&u1)[j], ((__half2*)&u2)[j]);
                        hh = __hfma2(a0, w1ah[0][j], hh);
                        hh = __hfma2(a1, w1ah[1][j], hh);
                        hh = __hfma2(a2, w1ah[2][j], hh);
                        hh = __hfma2(a3, w1ah[3][j], hh);
                        sum2[j] = __hadd2(sum2[j], hh);
                        sq2[j]  = __hfma2(hh, hh, sq2[j]);
                    }
                }
            }
        }
#pragma unroll
        for (int j = 0; j < 4; j++) {
            float2 fs = __half22float2(sum2[j]);
            float2 fq = __half22float2(sq2[j]);
            sacc[2*j]   += fs.x; sacc[2*j+1] += fs.y;
            qacc[2*j]   += fq.x; qacc[2*j+1] += fq.y;
        }
    }

#pragma unroll
    for (int j = 0; j < 8; j++) {
        atomicAdd(&bsum[ch + j], sacc[j]);
        atomicAdd(&bsq [ch + j], qacc[j]);
    }
    __syncthreads();
    if (tid < H) {
        atomicAdd(&g_sum[tid], bsum[tid]);
        atomicAdd(&g_sq[tid],  bsq[tid]);
    }

    // last-CTA finalize: stats over h' = h - b1; var(h)=var(h'), b1 absorbed into B_fold
    __threadfence();
    if (tid == 0) {
        unsigned prev = atomicAdd(&g_done, 1u);
        is_last = (prev == gridDim.x - 1);
    }
    __syncthreads();
    if (is_last && tid < H) {
        float mup = __ldcg(&g_sum[tid]) * invE;
        float var = __ldcg(&g_sq[tid]) * invE - mup * mup;
        float inv = rsqrtf(var + 1e-5f);
        float A = gamma[tid] * inv;
        g_A[tid] = A;
        g_B[tid] = beta[tid] - mup * A;
    }
}

// ---------------- pass B: 2 edges/warp, half2 attr term, fp32 affine/dot ----------------
__global__ void __launch_bounds__(256, 3) pass_b_kernel(
    const float* __restrict__ ea,
    const float* __restrict__ W1,
    const int* __restrict__ eidx,
    const float* __restrict__ W2,   // [128]
    const float* __restrict__ b2,   // [1]
    float* __restrict__ out,        // [E]
    int E, int Bm1)
{
    __shared__ float obuf[8][32];
    const int tid  = threadIdx.x;
    const int lane = tid & 31;
    const int wrp  = tid >> 5;
    const int hf   = lane >> 4;
    const int sub  = lane & 15;
    const int ch   = sub * 8;

    __half2 w1ah[4][4];
#pragma unroll
    for (int k = 0; k < 4; k++) {
        float4 v0 = *(const float4*)&W1[(128 + k) * H + ch];
        float4 v1 = *(const float4*)&W1[(128 + k) * H + ch + 4];
        w1ah[k][0] = __floats2half2_rn(v0.x, v0.y);
        w1ah[k][1] = __floats2half2_rn(v0.z, v0.w);
        w1ah[k][2] = __floats2half2_rn(v1.x, v1.y);
        w1ah[k][3] = __floats2half2_rn(v1.z, v1.w);
    }
    float Av[8], Bv[8], w2v[8];
    {
        float4 t0 = *(const float4*)&g_A[ch];  float4 t1 = *(const float4*)&g_A[ch+4];
        Av[0]=t0.x; Av[1]=t0.y; Av[2]=t0.z; Av[3]=t0.w; Av[4]=t1.x; Av[5]=t1.y; Av[6]=t1.z; Av[7]=t1.w;
        float4 u0 = *(const float4*)&g_B[ch];  float4 u1 = *(const float4*)&g_B[ch+4];
        Bv[0]=u0.x; Bv[1]=u0.y; Bv[2]=u0.z; Bv[3]=u0.w; Bv[4]=u1.x; Bv[5]=u1.y; Bv[6]=u1.z; Bv[7]=u1.w;
        float4 s0 = *(const float4*)&W2[ch];   float4 s1 = *(const float4*)&W2[ch+4];
        w2v[0]=s0.x; w2v[1]=s0.y; w2v[2]=s0.z; w2v[3]=s0.w; w2v[4]=s1.x; w2v[5]=s1.y; w2v[6]=s1.z; w2v[7]=s1.w;
    }
    const float b2v = b2[0];

    const int nwarps = gridDim.x * 8;
    const int gw = blockIdx.x * 8 + wrp;
    const int nchunks = (E + 31) >> 5;

    for (int chk = gw; chk < nchunks; chk += nwarps) {
        const int ebase = chk << 5;
        int e_l = ebase + lane;
        int s = 0, d = 0;
        if (e_l < E) { s = eidx[e_l]; d = eidx[(size_t)E + e_l]; }
        int batch = min(max(s >> 11, 0), Bm1);
        int off = batch << 11;
        int si = (s & NMASK) + off;
        int di = (d & NMASK) + off;

        if (ebase + 32 <= E) {
#pragma unroll 1
            for (int ii = 0; ii < 16; ii += 2) {
                uint4 u1[2], u2[2]; float4 av[2];
#pragma unroll
                for (int b = 0; b < 2; b++) {
                    int srcl = 2 * (ii + b) + hf;
                    int sii = __shfl_sync(FULL, si, srcl);
                    int dii = __shfl_sync(FULL, di, srcl);
                    u1[b] = *(const uint4*)&g_P[(size_t)sii * 256 + ch];
                    u2[b] = *(const uint4*)&g_P[(size_t)dii * 256 + 128 + ch];
                    av[b] = *(const float4*)&ea[(size_t)(ebase + srcl) * 4];
                }
#pragma unroll
                for (int b = 0; b < 2; b++) {
                    __half2 a0 = __floats2half2_rn(av[b].x, av[b].x);
                    __half2 a1 = __floats2half2_rn(av[b].y, av[b].y);
                    __half2 a2 = __floats2half2_rn(av[b].z, av[b].z);
                    __half2 a3 = __floats2half2_rn(av[b].w, av[b].w);
                    float r = 0.f;
#pragma unroll
                    for (int j = 0; j < 4; j++) {
                        __half2 hh = __hadd2(((__half2*)&u1[b])[j], ((__half2*)&u2[b])[j]);
                        hh = __hfma2(a0, w1ah[0][j], hh);
                        hh = __hfma2(a1, w1ah[1][j], hh);
                        hh = __hfma2(a2, w1ah[2][j], hh);
                        hh = __hfma2(a3, w1ah[3][j], hh);
                        float2 f = __half22float2(hh);
                        float t0 = fmaf(Av[2*j],   f.x, Bv[2*j]);
                        float t1 = fmaf(Av[2*j+1], f.y, Bv[2*j+1]);
                        t0 = (t0 >= 0.f) ? t0 : 0.2f * t0;
                        t1 = (t1 >= 0.f) ? t1 : 0.2f * t1;
                        r = fmaf(t0, w2v[2*j], r);
                        r = fmaf(t1, w2v[2*j+1], r);
                    }
#pragma unroll
                    for (int o = 8; o > 0; o >>= 1)
                        r += __shfl_xor_sync(FULL, r, o);
                    if (sub == 0) obuf[wrp][2 * (ii + b) + hf] = r + b2v;
                }
            }
            __syncwarp();
            out[ebase + lane] = obuf[wrp][lane];
            __syncwarp();
        } else {
            const int cnt = E - ebase;
            for (int i2 = 0; i2 < cnt; i2 += 2) {
                int srcl = min(i2 + hf, cnt - 1);
                int sii = __shfl_sync(FULL, si, srcl);
                int dii = __shfl_sync(FULL, di, srcl);
                uint4 u1 = *(const uint4*)&g_P[(size_t)sii * 256 + ch];
                uint4 u2 = *(const uint4*)&g_P[(size_t)dii * 256 + 128 + ch];
                float4 a = *(const float4*)&ea[(size_t)(ebase + srcl) * 4];
                __half2 a0 = __floats2half2_rn(a.x, a.x);
                __half2 a1 = __floats2half2_rn(a.y, a.y);
                __half2 a2 = __floats2half2_rn(a.z, a.z);
                __half2 a3 = __floats2half2_rn(a.w, a.w);
                float r = 0.f;
#pragma unroll
                for (int j = 0; j < 4; j++) {
                    __half2 hh = __hadd2(((__half2*)&u1)[j], ((__half2*)&u2)[j]);
                    hh = __hfma2(a0, w1ah[0][j], hh);
                    hh = __hfma2(a1, w1ah[1][j], hh);
                    hh = __hfma2(a2, w1ah[2][j], hh);
                    hh = __hfma2(a3, w1ah[3][j], hh);
                    float2 f = __half22float2(hh);
                    float t0 = fmaf(Av[2*j],   f.x, Bv[2*j]);
                    float t1 = fmaf(Av[2*j+1], f.y, Bv[2*j+1]);
                    t0 = (t0 >= 0.f) ? t0 : 0.2f * t0;
                    t1 = (t1 >= 0.f) ? t1 : 0.2f * t1;
                    r = fmaf(t0, w2v[2*j], r);
                    r = fmaf(t1, w2v[2*j+1], r);
                }
#pragma unroll
                for (int o = 8; o > 0; o >>= 1)
                    r += __shfl_xor_sync(FULL, r, o);
                if (sub == 0 && (i2 + hf) < cnt) obuf[wrp][i2 + hf] = r + b2v;
            }
            __syncwarp();
            if (lane < cnt) out[ebase + lane] = obuf[wrp][lane];
            __syncwarp();
        }
    }
}

extern "C" void kernel_launch(void* const* d_in, const int* in_sizes, int n_in,
                              void* d_out, int out_size)
{
    const float* z     = (const float*)d_in[0];
    const float* ea    = (const float*)d_in[1];
    const float* W1    = (const float*)d_in[2];
    const float* gamma = (const float*)d_in[4];
    const float* beta  = (const float*)d_in[5];
    const float* W2    = (const float*)d_in[6];
    const float* b2    = (const float*)d_in[7];
    const int*   eidx  = (const int*)d_in[8];     // int32 (JAX x64 disabled)

    const int E  = in_sizes[1] / 4;   // edge_attr is [E,4]
    const int BN = in_sizes[0] / 64;  // z is [B, N, 64]
    const int Bm1 = BN / 2048 - 1;
    float* out = (float*)d_out;

    node_gemm_kernel<<<(BN + 63) / 64, 256>>>(z, W1, BN);
    pass_a_kernel<<<888, 256>>>(ea, W1, eidx, gamma, beta, 1.0f / (float)E, E, Bm1);
    pass_b_kernel<<<888, 256>>>(ea, W1, eidx, W2, b2, out, E, Bm1);
}

// round 16
// speedup vs baseline: 1.2216x; 1.1267x over previous
#include <cuda_runtime.h>
#include <cuda_fp16.h>
#include <math.h>
#include <stdint.h>

#define H 128
#define NMASK 2047           // N = 2048
#define BN_MAX 65536
#define FULL 0xffffffffu

__device__ __half g_P[(size_t)BN_MAX * 256];
__device__ uint2  g_wfrag[4096];      // prebuilt HMMA B-fragments of Wc
__device__ float g_sum[H];
__device__ float g_sq[H];
__device__ float g_A[H];
__device__ float g_B[H];
__device__ unsigned g_done;

// ---------------- prep: build W fragments once (also resets stats) ----------------
// B(k16 x n8) col-major frag for mma.m16n8k16: b0 = Wc[k0+0/1][n], b1 = Wc[k0+8/9][n]
// with k0 = ks*16 + 2*(l&3), n = ntg*8 + (l>>2); Wc[k][c] = c<128 ? W1[k][c] : W1[64+k][c-128]
__global__ void prep_kernel(const float* __restrict__ W1) {
    int idx = blockIdx.x * 256 + threadIdx.x;   // 16 blocks x 256 = 4096
    if (idx < 4096) {
        int l   = idx & 31;
        int ntg = (idx >> 5) & 31;
        int ks  = idx >> 10;
        int gg  = l >> 2, tt = l & 3;
        int n   = ntg * 8 + gg;
        int k0  = ks * 16 + 2 * tt;
        int kb  = (n < 128) ? 0 : 64;
        int cc  = (n < 128) ? n : (n - 128);
        float w00 = W1[(kb + k0    ) * 128 + cc];
        float w01 = W1[(kb + k0 + 1) * 128 + cc];
        float w10 = W1[(kb + k0 + 8) * 128 + cc];
        float w11 = W1[(kb + k0 + 9) * 128 + cc];
        __half2 h0 = __floats2half2_rn(w00, w01);
        __half2 h1 = __floats2half2_rn(w10, w11);
        uint2 u;
        u.x = *(uint32_t*)&h0;
        u.y = *(uint32_t*)&h1;
        g_wfrag[idx] = u;
    }
    if (blockIdx.x == 0) {
        int t = threadIdx.x;
        if (t < H) { g_sum[t] = 0.f; g_sq[t] = 0.f; }
        if (t == 128) g_done = 0u;
    }
}

// ---------------- node GEMM via mma.sync HMMA (fragments preloaded coalesced) ----------------
#define ZS_PAD 72   // halves per row (144B): A-frag LDS banks all distinct

__device__ __forceinline__ void mma16816(float c[4],
                                         uint32_t a0, uint32_t a1, uint32_t a2, uint32_t a3,
                                         uint32_t b0, uint32_t b1) {
    asm volatile(
        "mma.sync.aligned.m16n8k16.row.col.f32.f16.f16.f32 "
        "{%0,%1,%2,%3}, {%4,%5,%6,%7}, {%8,%9}, {%0,%1,%2,%3};"
        : "+f"(c[0]), "+f"(c[1]), "+f"(c[2]), "+f"(c[3])
        : "r"(a0), "r"(a1), "r"(a2), "r"(a3), "r"(b0), "r"(b1));
}

__global__ void __launch_bounds__(256) node_gemm_kernel(
    const float* __restrict__ zf,   // [BN, 64]
    int BN)
{
    __shared__ __half zs[64 * ZS_PAD];        // 9216 B
    __shared__ uint2  wfrag[4096];            // [ks][ntg][lane], 32 KB

    const int tid  = threadIdx.x;
    const int lane = tid & 31;
    const int wid  = tid >> 5;
    const int nb   = blockIdx.x * 64;

    // coalesced copy of prebuilt fragments: 2048 uint4, 8 per thread
#pragma unroll
    for (int it = 0; it < 8; it++) {
        int i = tid + it * 256;
        ((uint4*)wfrag)[i] = ((const uint4*)g_wfrag)[i];
    }
    // z tile -> fp16 smem (row-major, padded)
#pragma unroll
    for (int it = 0; it < 4; it++) {
        int i = tid + it * 256;
        int node = i >> 4, k4 = i & 15;
        int nn = min(nb + node, BN - 1);
        float4 v = *(const float4*)&zf[(size_t)nn * 64 + k4 * 4];
        __half2 h01 = __floats2half2_rn(v.x, v.y);
        __half2 h23 = __floats2half2_rn(v.z, v.w);
        uint2 u;
        u.x = *(uint32_t*)&h01;
        u.y = *(uint32_t*)&h23;
        *(uint2*)&zs[node * ZS_PAD + k4 * 4] = u;
    }
    __syncthreads();

    const int g  = lane >> 2;
    const int tg = lane & 3;
    const int m0  = (wid >> 1) * 16;       // warp M base (nodes)
    const int n0t = (wid & 1) * 16;        // warp N base (8-col tiles)

    float c[16][4];
#pragma unroll
    for (int nt = 0; nt < 16; nt++)
#pragma unroll
        for (int j = 0; j < 4; j++) c[nt][j] = 0.f;

#pragma unroll
    for (int ks = 0; ks < 4; ks++) {
        const int r0 = m0 + g;
        const int cc = ks * 16 + 2 * tg;
        uint32_t a0 = *(const uint32_t*)&zs[r0 * ZS_PAD + cc];
        uint32_t a1 = *(const uint32_t*)&zs[(r0 + 8) * ZS_PAD + cc];
        uint32_t a2 = *(const uint32_t*)&zs[r0 * ZS_PAD + cc + 8];
        uint32_t a3 = *(const uint32_t*)&zs[(r0 + 8) * ZS_PAD + cc + 8];
#pragma unroll
        for (int nt = 0; nt < 16; nt++) {
            uint2 b = wfrag[(ks * 32 + n0t + nt) * 32 + lane];
            mma16816(c[nt], a0, a1, a2, a3, b.x, b.y);
        }
    }

#pragma unroll
    for (int nt = 0; nt < 16; nt++) {
        int ncol  = (n0t + nt) * 8 + 2 * tg;
        int node0 = nb + m0 + g;
        __half2 lo = __floats2half2_rn(c[nt][0], c[nt][1]);
        __half2 hi = __floats2half2_rn(c[nt][2], c[nt][3]);
        if (node0 < BN)
            *(__half2*)&g_P[(size_t)node0 * 256 + ncol] = lo;
        if (node0 + 8 < BN)
            *(__half2*)&g_P[(size_t)(node0 + 8) * 256 + ncol] = hi;
    }
}

// ---------------- pass A: 2 edges/warp, half2 math, BN stats over h' (no b1); last block finalizes ----------------
__global__ void __launch_bounds__(256, 3) pass_a_kernel(
    const float* __restrict__ ea,   // [E,4]
    const float* __restrict__ W1,   // [132,128]
    const int* __restrict__ eidx,   // [2,E] int32
    const float* __restrict__ gamma,
    const float* __restrict__ beta,
    float invE,
    int E, int Bm1)
{
    __shared__ float bsum[H], bsq[H];
    __shared__ bool is_last;
    const int tid  = threadIdx.x;
    const int lane = tid & 31;
    const int wrp  = tid >> 5;
    const int hf   = lane >> 4;
    const int sub  = lane & 15;
    const int ch   = sub * 8;
    if (tid < H) { bsum[tid] = 0.f; bsq[tid] = 0.f; }
    __syncthreads();

    __half2 w1ah[4][4];
#pragma unroll
    for (int k = 0; k < 4; k++) {
        float4 v0 = *(const float4*)&W1[(128 + k) * H + ch];
        float4 v1 = *(const float4*)&W1[(128 + k) * H + ch + 4];
        w1ah[k][0] = __floats2half2_rn(v0.x, v0.y);
        w1ah[k][1] = __floats2half2_rn(v0.z, v0.w);
        w1ah[k][2] = __floats2half2_rn(v1.x, v1.y);
        w1ah[k][3] = __floats2half2_rn(v1.z, v1.w);
    }

    float sacc[8], qacc[8];
#pragma unroll
    for (int j = 0; j < 8; j++) { sacc[j] = 0.f; qacc[j] = 0.f; }
    const __half2 z2 = __float2half2_rn(0.f);

    const int nwarps = gridDim.x * 8;
    const int gw = blockIdx.x * 8 + wrp;
    const int nchunks = (E + 31) >> 5;

    for (int chk = gw; chk < nchunks; chk += nwarps) {
        const int ebase = chk << 5;
        int e_l = ebase + lane;
        int s = 0, d = 0;
        if (e_l < E) { s = eidx[e_l]; d = eidx[(size_t)E + e_l]; }
        int batch = min(max(s >> 11, 0), Bm1);
        int off = batch << 11;
        int si = (s & NMASK) + off;
        int di = (d & NMASK) + off;

        __half2 sum2[4] = {z2, z2, z2, z2};
        __half2 sq2[4]  = {z2, z2, z2, z2};

        if (ebase + 32 <= E) {
#pragma unroll 1
            for (int ii = 0; ii < 16; ii += 2) {
                uint4 u1[2], u2[2]; float4 av[2];
#pragma unroll
                for (int b = 0; b < 2; b++) {
                    int srcl = 2 * (ii + b) + hf;
                    int sii = __shfl_sync(FULL, si, srcl);
                    int dii = __shfl_sync(FULL, di, srcl);
                    u1[b] = *(const uint4*)&g_P[(size_t)sii * 256 + ch];
                    u2[b] = *(const uint4*)&g_P[(size_t)dii * 256 + 128 + ch];
                    av[b] = *(const float4*)&ea[(size_t)(ebase + srcl) * 4];
                }
#pragma unroll
                for (int b = 0; b < 2; b++) {
                    __half2 a0 = __floats2half2_rn(av[b].x, av[b].x);
                    __half2 a1 = __floats2half2_rn(av[b].y, av[b].y);
                    __half2 a2 = __floats2half2_rn(av[b].z, av[b].z);
                    __half2 a3 = __floats2half2_rn(av[b].w, av[b].w);
#pragma unroll
                    for (int j = 0; j < 4; j++) {
                        __half2 hh = __hadd2(((__half2*)&u1[b])[j], ((__half2*)&u2[b])[j]);
                        hh = __hfma2(a0, w1ah[0][j], hh);
                        hh = __hfma2(a1, w1ah[1][j], hh);
                        hh = __hfma2(a2, w1ah[2][j], hh);
                        hh = __hfma2(a3, w1ah[3][j], hh);
                        sum2[j] = __hadd2(sum2[j], hh);
                        sq2[j]  = __hfma2(hh, hh, sq2[j]);
                    }
                }
            }
        } else {
            const int cnt = E - ebase;
            for (int i2 = 0; i2 < cnt; i2 += 2) {
                int srcl = min(i2 + hf, cnt - 1);
                int sii = __shfl_sync(FULL, si, srcl);
                int dii = __shfl_sync(FULL, di, srcl);
                uint4 u1 = *(const uint4*)&g_P[(size_t)sii * 256 + ch];
                uint4 u2 = *(const uint4*)&g_P[(size_t)dii * 256 + 128 + ch];
                float4 a = *(const float4*)&ea[(size_t)(ebase + srcl) * 4];
                if (i2 + hf < cnt) {
                    __half2 a0 = __floats2half2_rn(a.x, a.x);
                    __half2 a1 = __floats2half2_rn(a.y, a.y);
                    __half2 a2 = __floats2half2_rn(a.z, a.z);
                    __half2 a3 = __floats2half2_rn(a.w, a.w);
#pragma unroll
                    for (int j = 0; j < 4; j++) {
                        __half2 hh = __hadd2(((__half2*)&u1)[j], ((__half2*)&u2)[j]);
                        hh = __hfma2(a0, w1ah[0][j], hh);
                        hh = __hfma2(a1, w1ah[1][j], hh);
                        hh = __hfma2(a2, w1ah[2][j], hh);
                        hh = __hfma2(a3, w1ah[3][j], hh);
                        sum2[j] = __hadd2(sum2[j], hh);
                        sq2[j]  = __hfma2(hh, hh, sq2[j]);
                    }
                }
            }
        }
#pragma unroll
        for (int j = 0; j < 4; j++) {
            float2 fs = __half22float2(sum2[j]);
            float2 fq = __half22float2(sq2[j]);
            sacc[2*j]   += fs.x; sacc[2*j+1] += fs.y;
            qacc[2*j]   += fq.x; qacc[2*j+1] += fq.y;
        }
    }

#pragma unroll
    for (int j = 0; j < 8; j++) {
        atomicAdd(&bsum[ch + j], sacc[j]);
        atomicAdd(&bsq [ch + j], qacc[j]);
    }
    __syncthreads();
    if (tid < H) {
        atomicAdd(&g_sum[tid], bsum[tid]);
        atomicAdd(&g_sq[tid],  bsq[tid]);
    }

    // last-CTA finalize: stats over h' = h - b1; var(h)=var(h'), b1 absorbed into B_fold
    __threadfence();
    if (tid == 0) {
        unsigned prev = atomicAdd(&g_done, 1u);
        is_last = (prev == gridDim.x - 1);
    }
    __syncthreads();
    if (is_last && tid < H) {
        float mup = __ldcg(&g_sum[tid]) * invE;
        float var = __ldcg(&g_sq[tid]) * invE - mup * mup;
        float inv = rsqrtf(var + 1e-5f);
        float A = gamma[tid] * inv;
        g_A[tid] = A;
        g_B[tid] = beta[tid] - mup * A;
    }
}

// ---------------- pass B: 2 edges/warp, half2 attr term, fp32 affine/dot ----------------
__global__ void __launch_bounds__(256, 3) pass_b_kernel(
    const float* __restrict__ ea,
    const float* __restrict__ W1,
    const int* __restrict__ eidx,
    const float* __restrict__ W2,   // [128]
    const float* __restrict__ b2,   // [1]
    float* __restrict__ out,        // [E]
    int E, int Bm1)
{
    __shared__ float obuf[8][32];
    const int tid  = threadIdx.x;
    const int lane = tid & 31;
    const int wrp  = tid >> 5;
    const int hf   = lane >> 4;
    const int sub  = lane & 15;
    const int ch   = sub * 8;

    __half2 w1ah[4][4];
#pragma unroll
    for (int k = 0; k < 4; k++) {
        float4 v0 = *(const float4*)&W1[(128 + k) * H + ch];
        float4 v1 = *(const float4*)&W1[(128 + k) * H + ch + 4];
        w1ah[k][0] = __floats2half2_rn(v0.x, v0.y);
        w1ah[k][1] = __floats2half2_rn(v0.z, v0.w);
        w1ah[k][2] = __floats2half2_rn(v1.x, v1.y);
        w1ah[k][3] = __floats2half2_rn(v1.z, v1.w);
    }
    float Av[8], Bv[8], w2v[8];
    {
        float4 t0 = *(const float4*)&g_A[ch];  float4 t1 = *(const float4*)&g_A[ch+4];
        Av[0]=t0.x; Av[1]=t0.y; Av[2]=t0.z; Av[3]=t0.w; Av[4]=t1.x; Av[5]=t1.y; Av[6]=t1.z; Av[7]=t1.w;
        float4 u0 = *(const float4*)&g_B[ch];  float4 u1 = *(const float4*)&g_B[ch+4];
        Bv[0]=u0.x; Bv[1]=u0.y; Bv[2]=u0.z; Bv[3]=u0.w; Bv[4]=u1.x; Bv[5]=u1.y; Bv[6]=u1.z; Bv[7]=u1.w;
        float4 s0 = *(const float4*)&W2[ch];   float4 s1 = *(const float4*)&W2[ch+4];
        w2v[0]=s0.x; w2v[1]=s0.y; w2v[2]=s0.z; w2v[3]=s0.w; w2v[4]=s1.x; w2v[5]=s1.y; w2v[6]=s1.z; w2v[7]=s1.w;
    }
    const float b2v = b2[0];

    const int nwarps = gridDim.x * 8;
    const int gw = blockIdx.x * 8 + wrp;
    const int nchunks = (E + 31) >> 5;

    for (int chk = gw; chk < nchunks; chk += nwarps) {
        const int ebase = chk << 5;
        int e_l = ebase + lane;
        int s = 0, d = 0;
        if (e_l < E) { s = eidx[e_l]; d = eidx[(size_t)E + e_l]; }
        int batch = min(max(s >> 11, 0), Bm1);
        int off = batch << 11;
        int si = (s & NMASK) + off;
        int di = (d & NMASK) + off;

        if (ebase + 32 <= E) {
#pragma unroll 1
            for (int ii = 0; ii < 16; ii += 2) {
                uint4 u1[2], u2[2]; float4 av[2];
#pragma unroll
                for (int b = 0; b < 2; b++) {
                    int srcl = 2 * (ii + b) + hf;
                    int sii = __shfl_sync(FULL, si, srcl);
                    int dii = __shfl_sync(FULL, di, srcl);
                    u1[b] = *(const uint4*)&g_P[(size_t)sii * 256 + ch];
                    u2[b] = *(const uint4*)&g_P[(size_t)dii * 256 + 128 + ch];
                    av[b] = *(const float4*)&ea[(size_t)(ebase + srcl) * 4];
                }
#pragma unroll
                for (int b = 0; b < 2; b++) {
                    __half2 a0 = __floats2half2_rn(av[b].x, av[b].x);
                    __half2 a1 = __floats2half2_rn(av[b].y, av[b].y);
                    __half2 a2 = __floats2half2_rn(av[b].z, av[b].z);
                    __half2 a3 = __floats2half2_rn(av[b].w, av[b].w);
                    float r = 0.f;
#pragma unroll
                    for (int j = 0; j < 4; j++) {
                        __half2 hh = __hadd2(((__half2*)&u1[b])[j], ((__half2*)&u2[b])[j]);
                        hh = __hfma2(a0, w1ah[0][j], hh);
                        hh = __hfma2(a1, w1ah[1][j], hh);
                        hh = __hfma2(a2, w1ah[2][j], hh);
                        hh = __hfma2(a3, w1ah[3][j], hh);
                        float2 f = __half22float2(hh);
                        float t0 = fmaf(Av[2*j],   f.x, Bv[2*j]);
                        float t1 = fmaf(Av[2*j+1], f.y, Bv[2*j+1]);
                        t0 = (t0 >= 0.f) ? t0 : 0.2f * t0;
                        t1 = (t1 >= 0.f) ? t1 : 0.2f * t1;
                        r = fmaf(t0, w2v[2*j], r);
                        r = fmaf(t1, w2v[2*j+1], r);
                    }
#pragma unroll
                    for (int o = 8; o > 0; o >>= 1)
                        r += __shfl_xor_sync(FULL, r, o);
                    if (sub == 0) obuf[wrp][2 * (ii + b) + hf] = r + b2v;
                }
            }
            __syncwarp();
            out[ebase + lane] = obuf[wrp][lane];
            __syncwarp();
        } else {
            const int cnt = E - ebase;
            for (int i2 = 0; i2 < cnt; i2 += 2) {
                int srcl = min(i2 + hf, cnt - 1);
                int sii = __shfl_sync(FULL, si, srcl);
                int dii = __shfl_sync(FULL, di, srcl);
                uint4 u1 = *(const uint4*)&g_P[(size_t)sii * 256 + ch];
                uint4 u2 = *(const uint4*)&g_P[(size_t)dii * 256 + 128 + ch];
                float4 a = *(const float4*)&ea[(size_t)(ebase + srcl) * 4];
                __half2 a0 = __floats2half2_rn(a.x, a.x);
                __half2 a1 = __floats2half2_rn(a.y, a.y);
                __half2 a2 = __floats2half2_rn(a.z, a.z);
                __half2 a3 = __floats2half2_rn(a.w, a.w);
                float r = 0.f;
#pragma unroll
                for (int j = 0; j < 4; j++) {
                    __half2 hh = __hadd2(((__half2*)&u1)[j], ((__half2*)&u2)[j]);
                    hh = __hfma2(a0, w1ah[0][j], hh);
                    hh = __hfma2(a1, w1ah[1][j], hh);
                    hh = __hfma2(a2, w1ah[2][j], hh);
                    hh = __hfma2(a3, w1ah[3][j], hh);
                    float2 f = __half22float2(hh);
                    float t0 = fmaf(Av[2*j],   f.x, Bv[2*j]);
                    float t1 = fmaf(Av[2*j+1], f.y, Bv[2*j+1]);
                    t0 = (t0 >= 0.f) ? t0 : 0.2f * t0;
                    t1 = (t1 >= 0.f) ? t1 : 0.2f * t1;
                    r = fmaf(t0, w2v[2*j], r);
                    r = fmaf(t1, w2v[2*j+1], r);
                }
#pragma unroll
                for (int o = 8; o > 0; o >>= 1)
                    r += __shfl_xor_sync(FULL, r, o);
                if (sub == 0 && (i2 + hf) < cnt) obuf[wrp][i2 + hf] = r + b2v;
            }
            __syncwarp();
            if (lane < cnt) out[ebase + lane] = obuf[wrp][lane];
            __syncwarp();
        }
    }
}

extern "C" void kernel_launch(void* const* d_in, const int* in_sizes, int n_in,
                              void* d_out, int out_size)
{
    const float* z     = (const float*)d_in[0];
    const float* ea    = (const float*)d_in[1];
    const float* W1    = (const float*)d_in[2];
    const float* gamma = (const float*)d_in[4];
    const float* beta  = (const float*)d_in[5];
    const float* W2    = (const float*)d_in[6];
    const float* b2    = (const float*)d_in[7];
    const int*   eidx  = (const int*)d_in[8];     // int32 (JAX x64 disabled)

    const int E  = in_sizes[1] / 4;   // edge_attr is [E,4]
    const int BN = in_sizes[0] / 64;  // z is [B, N, 64]
    const int Bm1 = BN / 2048 - 1;
    float* out = (float*)d_out;

    prep_kernel<<<16, 256>>>(W1);
    node_gemm_kernel<<<(BN + 63) / 64, 256>>>(z, BN);
    pass_a_kernel<<<888, 256>>>(ea, W1, eidx, gamma, beta, 1.0f / (float)E, E, Bm1);
    pass_b_kernel<<<888, 256>>>(ea, W1, eidx, W2, b2, out, E, Bm1);
}